// round 13
// baseline (speedup 1.0000x reference)
#include <cuda_runtime.h>
#include <cstdint>

// TropicalConv2D: out[b,c,h,w] = max_{di,dj in [-2,2]} x[b,c,h+di,w+dj] + kflip[c,di+2,dj+2]
// kflip[a,b] = kernel[c,0,4-a,4-b], OOB = -inf.
// Fixed: B=8, C=32, H=W=224, K=5, stride=1, pad=2, dil=1.

#define HH 224
#define WW 224
#define CC 32
#define BB 8

// Block tile: 112 (w) x 32 (h) outputs, 28x8 threads, 4x4 outputs/thread.
// smem window: 36 rows x 120 cols, stile col s = global col (bx*112 - 2 + s).
// Staging: lane-mapped float4 chunks at global col ≡ 0 mod 4, stored at s = lane*4 - 2
// (two float2 STS; 4-float guard pad in front absorbs s = -2).
#define SROWS 36
#define SCOLW 120

// -inf x4 as bit patterns (constant initializer; reinterpret at use).
__device__ __align__(16) const unsigned int d_nivec[4] =
    {0xff800000u, 0xff800000u, 0xff800000u, 0xff800000u};

// Constant-index component select over two float4 regs (folds to a direct register
// access after unrolling — no xr[] copy MOVs).
__device__ __forceinline__ float xc(const float4& q0, const float4& q1, const int k) {
    return (k == 0) ? q0.x : (k == 1) ? q0.y : (k == 2) ? q0.z : (k == 3) ? q0.w
         : (k == 4) ? q1.x : (k == 5) ? q1.y : (k == 6) ? q1.z : q1.w;
}

extern "C" __global__ void __launch_bounds__(224, 5)
tropical_conv2d_kernel(const float* __restrict__ x,
                       const float* __restrict__ kern,
                       float* __restrict__ out) {
    __shared__ __align__(16) float smem_raw[4 + SROWS * SCOLW];
    float* const stile = smem_raw + 4;   // stile[-2] valid (guard pad)

    const int tx = threadIdx.x;                 // 0..27
    const int ty = threadIdx.y;                 // 0..7
    const int tid = ty * 28 + tx;               // 0..223
    const int plane = blockIdx.z;               // b*C + c
    const int c = plane & (CC - 1);

    const float* xp = x + (size_t)plane * (HH * WW);

    // Flipped per-channel weights (block-uniform): wf[t] = kernel[c*25 + 24 - t]
    float wf[25];
    const float* kc = kern + c * 25;
#pragma unroll
    for (int t = 0; t < 25; ++t) wf[t] = __ldg(kc + (24 - t));

    // ---- Stage 36x120 window; warp w handles rows w, w+7, ..., lane = float4 chunk ----
    {
        const int wid = tid >> 5;               // 0..6
        const int lane = tid & 31;              // 0..31; chunks 0..29 active
        const int row0 = blockIdx.y * 32 - 2;
        const int gc = blockIdx.x * 112 - 4 + lane * 4;      // ≡ 0 mod 4
        const bool laneOK = (lane < 30);
        const bool colOK = ((unsigned)gc < (unsigned)WW);    // chunk fully in or out
        float* const sdst0 = &stile[lane * 4 - 2];
#pragma unroll
        for (int k = 0; k < 6; ++k) {
            const int ry = wid + k * 7;                      // 0..41
            if (laneOK && ry < SROWS) {
                const int gy = row0 + ry;
                const bool ok = colOK && ((unsigned)gy < (unsigned)HH);
                const float4* src = ok
                    ? reinterpret_cast<const float4*>(xp + gy * WW + gc)
                    : reinterpret_cast<const float4*>(d_nivec);
                const float4 v = *src;
                float* dst = sdst0 + ry * SCOLW;
                *reinterpret_cast<float2*>(dst)     = make_float2(v.x, v.y);
                *reinterpret_cast<float2*>(dst + 2) = make_float2(v.z, v.w);
            }
        }
    }

    __syncthreads();

    float acc[4][4];   // initialized at first tap (a==0, j==0)

    // Thread window: smem rows ty*4 .. ty*4+7, cols tx*4 .. tx*4+7 (16B-aligned).
    const float* sb = &stile[(ty * 4) * SCOLW + tx * 4];
#pragma unroll
    for (int r = 0; r < 8; ++r) {
        const float4 q0 = *reinterpret_cast<const float4*>(sb + r * SCOLW + 0);
        const float4 q1 = *reinterpret_cast<const float4*>(sb + r * SCOLW + 4);
#pragma unroll
        for (int oh = 0; oh < 4; ++oh) {
            const int a = r - oh;          // compile-time after unroll
            if (a >= 0 && a <= 4) {
#pragma unroll
                for (int j = 0; j < 5; ++j) {
                    const float wv = wf[a * 5 + j];
#pragma unroll
                    for (int ow = 0; ow < 4; ++ow) {
                        const float s = xc(q0, q1, ow + j) + wv;
                        if (a == 0 && j == 0)
                            acc[oh][ow] = s;
                        else
                            acc[oh][ow] = fmaxf(acc[oh][ow], s);
                    }
                }
            }
        }
    }

    // Store 4 rows x 4 cols (float4-aligned).
    const int w0 = blockIdx.x * 112 + tx * 4;
    const int h0 = blockIdx.y * 32 + ty * 4;
    float* op = out + (size_t)plane * (HH * WW);
#pragma unroll
    for (int oh = 0; oh < 4; ++oh) {
        float4 v = make_float4(acc[oh][0], acc[oh][1], acc[oh][2], acc[oh][3]);
        *reinterpret_cast<float4*>(op + (h0 + oh) * WW + w0) = v;
    }
}

extern "C" void kernel_launch(void* const* d_in, const int* in_sizes, int n_in,
                              void* d_out, int out_size) {
    const float* x = (const float*)d_in[0];
    const float* kern = (const float*)d_in[1];
    float* out = (float*)d_out;

    dim3 block(28, 8, 1);          // 224 threads, 4x4 outputs each -> 112x32 tile
    dim3 grid(2, 7, BB * CC);      // 224 cols, 224 rows, 256 planes
    tropical_conv2d_kernel<<<grid, block>>>(x, kern, out);
}